// round 13
// baseline (speedup 1.0000x reference)
#include <cuda_runtime.h>
#include <cuda_bf16.h>
#include <cstdint>
#include <cfloat>

#define VOCAB   500000
#define EMB_D   128
#define HID     128
#define STEPS   64
#define NTILES  3907          // ceil(VOCAB/128)
#define K2CTAS  148
#define K1CTAS  4

// ---------------- device globals (scratch; no allocation allowed) ----------
__device__ float               g_cs[STEPS * HID];    // cell states [step][k]
__device__ __align__(16) float g_xh[2][256];         // state exchange buffers
__device__ unsigned int        g_cnt = 0;            // doorbell (reset at end)
__device__ int                 g_fin = 0;            // k1 finish counter
__device__ unsigned long long  g_best[STEPS];        // (enc(score)<<32)|~idx
__device__ int                 g_done = 0;           // k2 last-CTA counter

// ---------------- helpers ---------------------------------------------------
__device__ __forceinline__ uint32_t enc_f32(float f) {
    uint32_t u = __float_as_uint(f);
    return (u & 0x80000000u) ? ~u : (u | 0x80000000u);
}
// fast activations (MUFU-based, ~1e-6 rel err; overflow-safe)
__device__ __forceinline__ float sig_fast(float x) {
    return __fdividef(1.0f, 1.0f + __expf(-x));
}
__device__ __forceinline__ float tanh_fast(float x) {
    return 1.0f - __fdividef(2.0f, __expf(2.0f * x) + 1.0f);
}
// split a float2 into bf16x2 hi and bf16x2 lo(residual)
__device__ __forceinline__ void split2(float2 v, uint32_t& hi, uint32_t& lo) {
    __nv_bfloat162 h = __floats2bfloat162_rn(v.x, v.y);
    hi = *(uint32_t*)&h;
    float rx = v.x - __bfloat162float(h.x);
    float ry = v.y - __bfloat162float(h.y);
    __nv_bfloat162 l = __floats2bfloat162_rn(rx, ry);
    lo = *(uint32_t*)&l;
}
// m16n8k16 row.col f32.bf16.bf16.f32
__device__ __forceinline__ void mma16816(float* c, const uint32_t* a,
                                         uint32_t b0, uint32_t b1) {
    asm volatile(
        "mma.sync.aligned.m16n8k16.row.col.f32.bf16.bf16.f32 "
        "{%0,%1,%2,%3}, {%4,%5,%6,%7}, {%8,%9}, {%0,%1,%2,%3};"
        : "+f"(c[0]), "+f"(c[1]), "+f"(c[2]), "+f"(c[3])
        : "r"(a[0]), "r"(a[1]), "r"(a[2]), "r"(a[3]), "r"(b0), "r"(b1));
}

// ============================================================================
// K1: 64 LSTM steps. 4 CTAs x 256 threads, L2 exchange.
//     - CTA r owns hidden j in [32r, 32r+32) = 128 gate rows.
//     - Thread (rp=tid>>2, part=tid&3) handles rows {rp, rp+64} x cols
//       [64*part, 64*part+64): 128 weight regs, 256B state reads -> 128 FMA.
//     - Publish: 32 epilogue lanes STG their c/h then per-lane
//       red.release.gpu.add(+1) on the doorbell (NO threadfence).
//     - Consume: warp 1 acquire-polls cnt >= 128*step, fetches state,
//       overlapping warp 0's epilogue.
// ============================================================================
__global__ void __launch_bounds__(256, 1)
k1_lstm(const float* __restrict__ embed,
        const float* __restrict__ w_ih,
        const float* __restrict__ w_hh,
        const float* __restrict__ inp,
        const float* __restrict__ b_ih,
        const float* __restrict__ b_hh,
        float* __restrict__ out, int write_cs) {
    __shared__ float xh[256];           // [c(128) ; h(128)]
    __shared__ float gates_sm[128];     // lr = g*32 + jloc
    __shared__ float Ksm[128];
    __shared__ float inp_sm[128];

    const int tid  = threadIdx.x;
    const int rank = blockIdx.x;

    const int rp    = tid >> 2;         // 0..63  (rows rp and rp+64)
    const int part  = tid & 3;          // column quarter (64 cols)
    const int jloc0 = rp & 31;
    const int grow0 = ((rp >> 5)    ) * 128 + 32 * rank + jloc0;  // gate 0/1
    const int grow1 = ((rp >> 5) + 2) * 128 + 32 * rank + jloc0;  // gate 2/3

    if (rank == 0 && tid < STEPS) g_best[tid] = 0ull;

    if (tid < 128) {
        inp_sm[tid]   = inp[tid];
        xh[tid]       = embed[tid];     // x0 = embed[<start>=0]
        xh[128 + tid] = 0.f;            // h0 = 0
    }

    // ---- weights: 2 rows x 64 cols per thread ----
    float w0[64], w1[64];
    #pragma unroll
    for (int cc = 0; cc < 64; ++cc) {
        int col = part * 64 + cc;
        if (col < 128) {
            w0[cc] = w_ih[grow0 * 256 + col];
            w1[cc] = w_ih[grow1 * 256 + col];
        } else {
            w0[cc] = w_hh[grow0 * 128 + (col - 128)];
            w1[cc] = w_hh[grow1 * 128 + (col - 128)];
        }
    }
    __syncthreads();

    // ---- fold K = b_ih + b_hh + W_ih[:,128:] @ inp (2 rows/thread) ----
    {
        const float* wr0 = w_ih + grow0 * 256 + 128 + part * 32;
        const float* wr1 = w_ih + grow1 * 256 + 128 + part * 32;
        float s0 = 0.f, s1 = 0.f;
        #pragma unroll 8
        for (int c = 0; c < 32; ++c) {
            float x = inp_sm[part * 32 + c];
            s0 = fmaf(wr0[c], x, s0);
            s1 = fmaf(wr1[c], x, s1);
        }
        s0 += __shfl_xor_sync(0xffffffffu, s0, 1);
        s0 += __shfl_xor_sync(0xffffffffu, s0, 2);
        s1 += __shfl_xor_sync(0xffffffffu, s1, 1);
        s1 += __shfl_xor_sync(0xffffffffu, s1, 2);
        if (part == 0) {
            Ksm[rp]      = s0 + b_ih[grow0] + b_hh[grow0];
            Ksm[rp + 64] = s1 + b_ih[grow1] + b_hh[grow1];
        }
    }
    __syncthreads();

    float c_reg = 0.f, k0v = 0.f, k1v = 0.f, k2v = 0.f, k3v = 0.f;
    if (tid < 32) {
        k0v = Ksm[tid]; k1v = Ksm[32 + tid];
        k2v = Ksm[64 + tid]; k3v = Ksm[96 + tid];
    }
    __syncthreads();

    for (int step = 0; step < STEPS; ++step) {
        // ---- warp 1: acquire-poll doorbell + fetch state (overlaps prev
        //      step's warp-0 epilogue; all other warps wait at the barrier) ----
        if (step > 0 && tid >= 32 && tid < 64) {
            const unsigned int tgt = 128u * (unsigned)step;
            unsigned int v;
            do {
                asm volatile("ld.acquire.gpu.global.u32 %0, [%1];"
                             : "=r"(v) : "l"(&g_cnt) : "memory");
            } while (v < tgt);
            const int ln = tid - 32;
            const float4* src = (const float4*)g_xh[step & 1];
            float4 a = __ldcg(src + ln);
            float4 b = __ldcg(src + ln + 32);
            ((float4*)xh)[ln]      = a;
            ((float4*)xh)[ln + 32] = b;
        }
        __syncthreads();                // xh ready

        // ---- dot: 2 rows x 64 cols per thread ----
        const float4* xv = (const float4*)&xh[part * 64];
        float a0 = 0.f, a1 = 0.f, b0 = 0.f, b1 = 0.f;
        #pragma unroll
        for (int qq = 0; qq < 16; qq += 2) {
            float4 v0 = xv[qq], v1 = xv[qq + 1];
            a0 = fmaf(w0[4*qq + 0], v0.x, a0); a1 = fmaf(w0[4*qq + 1], v0.y, a1);
            a0 = fmaf(w0[4*qq + 2], v0.z, a0); a1 = fmaf(w0[4*qq + 3], v0.w, a1);
            b0 = fmaf(w1[4*qq + 0], v0.x, b0); b1 = fmaf(w1[4*qq + 1], v0.y, b1);
            b0 = fmaf(w1[4*qq + 2], v0.z, b0); b1 = fmaf(w1[4*qq + 3], v0.w, b1);
            a0 = fmaf(w0[4*qq + 4], v1.x, a0); a1 = fmaf(w0[4*qq + 5], v1.y, a1);
            a0 = fmaf(w0[4*qq + 6], v1.z, a0); a1 = fmaf(w0[4*qq + 7], v1.w, a1);
            b0 = fmaf(w1[4*qq + 4], v1.x, b0); b1 = fmaf(w1[4*qq + 5], v1.y, b1);
            b0 = fmaf(w1[4*qq + 6], v1.z, b0); b1 = fmaf(w1[4*qq + 7], v1.w, b1);
        }
        float accA = a0 + a1, accB = b0 + b1;
        accA += __shfl_xor_sync(0xffffffffu, accA, 1);
        accA += __shfl_xor_sync(0xffffffffu, accA, 2);
        accB += __shfl_xor_sync(0xffffffffu, accB, 1);
        accB += __shfl_xor_sync(0xffffffffu, accB, 2);
        if (part == 0) {
            gates_sm[rp]      = accA;
            gates_sm[rp + 64] = accB;
        }
        __syncthreads();                // gates ready; xh reads done

        // ---- warp 0: epilogue + publish (no fence; per-lane release-RED) ----
        if (tid < 32) {
            const int j = 32 * rank + tid;
            float gi = gates_sm[tid]      + k0v;
            float gf = gates_sm[32 + tid] + k1v;
            float gg = gates_sm[64 + tid] + k2v;
            float go = gates_sm[96 + tid] + k3v;
            float iv = sig_fast(gi), fv = sig_fast(gf);
            float gv = tanh_fast(gg), ov = sig_fast(go);
            float c_new = fv * c_reg + iv * gv;
            float h_new = ov * tanh_fast(c_new);
            c_reg = c_new;
            if (write_cs) out[step * 128 + j] = c_new;
            g_cs[step * 128 + j] = c_new;
            if (step < STEPS - 1) {
                const int pn = (step + 1) & 1;
                g_xh[pn][j]       = c_new;    // x = c
                g_xh[pn][128 + j] = h_new;
                // release: orders THIS lane's two stores before the increment
                asm volatile("red.release.gpu.global.add.u32 [%0], %1;"
                             :: "l"(&g_cnt), "r"(1u) : "memory");
            }
        }
        // next iteration's top barrier separates epilogue from next dot
    }

    // ---- reset doorbell for next launch / graph replay (last CTA) ----
    if (tid == 0) {
        int r = atomicAdd(&g_fin, 1);
        if (r == K1CTAS - 1) {
            g_fin = 0;
            g_cnt = 0u;
            __threadfence();
        }
    }
}

// ============================================================================
// K2: persistent scorer (unchanged R8 winner). 148 CTAs x 256 threads.
//     bf16 3-segment mma.sync; running register argmax across all tiles.
// ============================================================================
__global__ void __launch_bounds__(256, 1)
k2_score(const float* __restrict__ embed, float* __restrict__ out, int out_size) {
    __shared__ uint4 sbfrag[2048];                  // [nc*8+kc][lane], 32KB
    __shared__ unsigned long long wb[8][STEPS];
    __shared__ int is_last;

    const int tid  = threadIdx.x;
    const int lane = tid & 31;
    const int w    = tid >> 5;
    const int q    = lane & 3;          // col-quad within fragment
    const int r4   = lane >> 2;         // fragment row 0..7

    // ---- build B fragments from g_cs into smem (once per CTA) ----
    {
        const float2* c2 = (const float2*)g_cs;
        #pragma unroll
        for (int it = 0; it < 8; ++it) {
            int idx  = tid + it * 256;
            int ln   = idx & 31;
            int kc   = (idx >> 5) & 7;
            int nc   = idx >> 8;
            int n    = nc * 8 + (ln >> 2);
            int qq   = ln & 3;
            float2 p01 = c2[n * 64 + kc * 8 + qq];
            float2 p23 = c2[n * 64 + kc * 8 + qq + 4];
            uint32_t h01, l01, h23, l23;
            split2(p01, h01, l01);
            split2(p23, h23, l23);
            sbfrag[idx] = make_uint4(h01, h23, l01, l23);
        }
    }
    __syncthreads();

    const float2* e2 = (const float2*)embed;
    float2 F[32];                       // raw A prefetch buffer (64 regs)

#define PREFETCH_TILE(TT) do {                                                 \
    int _r0 = (TT) * 128 + w * 16 + r4;                                        \
    int _r1 = _r0 + 8;                                                         \
    size_t _b0 = (size_t)((_r0 < VOCAB) ? _r0 : 0) * 64;                       \
    size_t _b1 = (size_t)((_r1 < VOCAB) ? _r1 : 0) * 64;                       \
    _Pragma("unroll")                                                          \
    for (int kc = 0; kc < 8; ++kc) {                                           \
        F[kc * 4 + 0] = e2[_b0 + kc * 8 + q];                                  \
        F[kc * 4 + 1] = e2[_b1 + kc * 8 + q];                                  \
        F[kc * 4 + 2] = e2[_b0 + kc * 8 + q + 4];                              \
        F[kc * 4 + 3] = e2[_b1 + kc * 8 + q + 4];                              \
    } } while (0)

    float bs[16]; int br[16];
    #pragma unroll
    for (int i = 0; i < 16; ++i) { bs[i] = -FLT_MAX; br[i] = 0; }

    int t = blockIdx.x;
    if (t < NTILES) PREFETCH_TILE(t);

    while (t < NTILES) {
        const int  row0 = t * 128 + w * 16 + r4;
        const int  row1 = row0 + 8;
        const bool v0 = row0 < VOCAB, v1 = row1 < VOCAB;

        uint32_t aH[8][4], aL[8][4];
        float ssq0 = 0.f, ssq1 = 0.f;
        const float2 z2 = make_float2(0.f, 0.f);
        #pragma unroll
        for (int kc = 0; kc < 8; ++kc) {
            float2 f00 = v0 ? F[kc * 4 + 0] : z2;
            float2 f10 = v1 ? F[kc * 4 + 1] : z2;
            float2 f01 = v0 ? F[kc * 4 + 2] : z2;
            float2 f11 = v1 ? F[kc * 4 + 3] : z2;
            ssq0 = fmaf(f00.x, f00.x, fmaf(f00.y, f00.y,
                    fmaf(f01.x, f01.x, fmaf(f01.y, f01.y, ssq0))));
            ssq1 = fmaf(f10.x, f10.x, fmaf(f10.y, f10.y,
                    fmaf(f11.x, f11.x, fmaf(f11.y, f11.y, ssq1))));
            split2(f00, aH[kc][0], aL[kc][0]);
            split2(f10, aH[kc][1], aL[kc][1]);
            split2(f01, aH[kc][2], aL[kc][2]);
            split2(f11, aH[kc][3], aL[kc][3]);
        }
        ssq0 += __shfl_xor_sync(0xffffffffu, ssq0, 1);
        ssq0 += __shfl_xor_sync(0xffffffffu, ssq0, 2);
        ssq1 += __shfl_xor_sync(0xffffffffu, ssq1, 1);
        ssq1 += __shfl_xor_sync(0xffffffffu, ssq1, 2);
        const float iv0 = 1.0f / fmaxf(sqrtf(ssq0), 1e-8f);
        const float iv1 = 1.0f / fmaxf(sqrtf(ssq1), 1e-8f);

        const int tn = t + K2CTAS;
        if (tn < NTILES) PREFETCH_TILE(tn);

        #pragma unroll
        for (int nc = 0; nc < 8; ++nc) {
            float c1[4]  = {0.f, 0.f, 0.f, 0.f};
            float c2a[4] = {0.f, 0.f, 0.f, 0.f};
            float c3[4]  = {0.f, 0.f, 0.f, 0.f};
            #pragma unroll
            for (int kc = 0; kc < 8; ++kc) {
                uint4 bb = sbfrag[(nc * 8 + kc) * 32 + lane];
                mma16816(c1,  aH[kc], bb.x, bb.y);   // hi*hi
                mma16816(c2a, aH[kc], bb.z, bb.w);   // hi*lo
                mma16816(c3,  aL[kc], bb.x, bb.y);   // lo*hi
            }
            #pragma unroll
            for (int e = 0; e < 2; ++e) {
                const int sl = nc * 2 + e;
                float s0 = v0 ? (c1[e]     + c2a[e]     + c3[e])     * iv0 : -FLT_MAX;
                float s1 = v1 ? (c1[2 + e] + c2a[2 + e] + c3[2 + e]) * iv1 : -FLT_MAX;
                if (s0 > bs[sl]) { bs[sl] = s0; br[sl] = row0; }
                if (s1 > bs[sl]) { bs[sl] = s1; br[sl] = row1; }
            }
        }
        t = tn;        // no barrier: warps free-run across tiles
    }

    // ---- single final reduction ----
    #pragma unroll
    for (int sl = 0; sl < 16; ++sl) {
        unsigned long long key =
            ((unsigned long long)enc_f32(bs[sl]) << 32) |
            (uint32_t)(~(uint32_t)br[sl]);
        #pragma unroll
        for (int off = 4; off < 32; off <<= 1) {
            unsigned long long o = __shfl_xor_sync(0xffffffffu, key, off);
            if (o > key) key = o;
        }
        if (r4 == 0) wb[w][(sl >> 1) * 8 + 2 * q + (sl & 1)] = key;
    }
    __syncthreads();
    if (tid < STEPS) {
        unsigned long long best = wb[0][tid];
        #pragma unroll
        for (int ww = 1; ww < 8; ++ww)
            if (wb[ww][tid] > best) best = wb[ww][tid];
        atomicMax(&g_best[tid], best);
    }

    // ---- last CTA decodes token ids ----
    __threadfence();
    __syncthreads();
    if (tid == 0) {
        int c = atomicAdd(&g_done, 1);
        is_last = (c == (int)gridDim.x - 1);
    }
    __syncthreads();
    if (is_last) {
        if (tid == 0) g_done = 0;
        __threadfence();
        if (tid < STEPS) {
            uint32_t idx = ~((uint32_t)(g_best[tid] & 0xffffffffu));
            out[(out_size - STEPS) + tid] = (float)idx;
        }
    }
#undef PREFETCH_TILE
}

// ============================================================================
extern "C" void kernel_launch(void* const* d_in, const int* in_sizes, int n_in,
                              void* d_out, int out_size) {
    const float* inp   = (const float*)d_in[0];
    const float* embed = (const float*)d_in[1];
    const float* w_ih  = (const float*)d_in[2];
    const float* w_hh  = (const float*)d_in[3];
    const float* b_ih  = (const float*)d_in[4];
    const float* b_hh  = (const float*)d_in[5];
    float* out = (float*)d_out;
    (void)in_sizes; (void)n_in;

    const int write_cs = (out_size >= STEPS * 128 + STEPS) ? 1 : 0;

    // Phase A: 4-CTA LSTM with release-RED doorbell exchange
    k1_lstm<<<K1CTAS, 256>>>(embed, w_ih, w_hh, inp, b_ih, b_hh, out, write_cs);

    // Phase B: persistent mma.sync scoring + argmax + decode
    k2_score<<<K2CTAS, 256>>>(embed, out, out_size);
}